// round 13
// baseline (speedup 1.0000x reference)
#include <cuda_runtime.h>
#include <cstdint>

#define BATCH 8
#define NPTS  4096
#define CH    128
#define KNN   16
#define NDS   2048
#define CAP   64     // per-thread u16 stack capacity
#define TPB   256
#define EPS   1e-3f  // conservative filter margin (approx filter domain)
#define TMARG 1e-4f  // termination margin (exact d2 domain, >> fp rounding)

// scratch (allocation-free rule: device globals)
__device__ float g_scores[BATCH * NPTS];
__device__ int   g_idx[BATCH * NDS];
__device__ int   g_zperm[BATCH * NPTS];

// XLA:GPU small-row reduction order for a 16-element row (shfl_down 8,4,2,1)
__device__ __forceinline__ float tree16(const float* v) {
    float s8[8], s4[4], s2[2];
    #pragma unroll
    for (int l = 0; l < 8; ++l) s8[l] = __fadd_rn(v[l], v[l + 8]);
    #pragma unroll
    for (int l = 0; l < 4; ++l) s4[l] = __fadd_rn(s8[l], s8[l + 4]);
    #pragma unroll
    for (int l = 0; l < 2; ++l) s2[l] = __fadd_rn(s4[l], s4[l + 2]);
    return __fadd_rn(s2[0], s2[1]);
}

__device__ __forceinline__ unsigned int fmap(float f) {
    unsigned int u = __float_as_uint(f);
    return u ^ (((unsigned int)(((int)u) >> 31)) | 0x80000000u);
}

// Sentinel = mapped(+inf) in high word: unmaps back to +inf.
#define SENTINEL 0xFF800000FFFFFFFFull

// ---------------------------------------------------------------------------
// Kernel 0: per-batch bitonic sort by z -> permutation (ascending z, idx ties)
// ---------------------------------------------------------------------------
__global__ void __launch_bounds__(1024) zsort_kernel(const float* __restrict__ x) {
    __shared__ unsigned long long sh[NPTS];
    const int b = blockIdx.x, tid = threadIdx.x;
    const float* zb = x + b * 3 * NPTS + 2 * NPTS;

    for (int i = tid; i < NPTS; i += 1024)
        sh[i] = (((unsigned long long)fmap(zb[i])) << 32) | (unsigned int)i;
    __syncthreads();

    for (int k = 2; k <= NPTS; k <<= 1) {
        for (int j = k >> 1; j > 0; j >>= 1) {
            #pragma unroll 2
            for (int p = tid; p < NPTS / 2; p += 1024) {
                int i = ((p & ~(j - 1)) << 1) | (p & (j - 1));
                int l = i | j;
                unsigned long long Av = sh[i], Bv = sh[l];
                bool up = ((i & k) == 0);
                if ((Av > Bv) == up) { sh[i] = Bv; sh[l] = Av; }
            }
            __syncthreads();
        }
    }
    for (int j = tid; j < NPTS; j += 1024)
        g_zperm[b * NPTS + j] = (int)(unsigned int)sh[j];
}

// ---------------------------------------------------------------------------
// Kernel 1: KNN score over z-SORTED candidates with exact early termination.
// Block = 128 queries (sorted slots) x 2 threads: h=0 scans rightward from
// the query slot, h=1 leftward. Hot loop (chunks of 8): approx conservative
// filter (3 FFMA + FSETP, EPS margin) -> push sorted idx to per-thread smem
// stack. Rare flushes recompute EXACT d2 (verified sequence) and keep the
// exact sorted top-16 as u64 (mapped_d2, ORIGINAL idx) keys. Termination:
// dz^2 lower-bounds d2; when chunk-end dz^2 > thrF(+TMARG) after a flush,
// all remaining candidates on this side are strictly worse -> stop.
// ---------------------------------------------------------------------------
__global__ void __launch_bounds__(TPB) knn_score_kernel(const float* __restrict__ x) {
    extern __shared__ unsigned char smem[];
    float4*         pts  = (float4*)smem;                         // 64KB sorted pts
    unsigned short* oidx = (unsigned short*)(smem + 65536);       // 8KB orig idx
    unsigned short* inv  = (unsigned short*)(smem + 73728);       // 8KB orig->sorted
    const unsigned  stkBase = 81920u;                             // 32KB stacks

    const int b   = blockIdx.y;
    const int tid = threadIdx.x;
    const int qt  = tid & 127;
    const int h   = tid >> 7;
    const float* xb = x + b * 3 * NPTS;
    const int* zp = g_zperm + b * NPTS;

    for (int j = tid; j < NPTS; j += TPB) {
        int oi = zp[j];
        float v0 = xb[oi], v1 = xb[NPTS + oi], v2 = xb[2 * NPTS + oi];
        float sq = __fadd_rn(__fadd_rn(__fmul_rn(v0, v0), __fmul_rn(v1, v1)),
                             __fmul_rn(v2, v2));
        pts[j] = make_float4(v0, v1, v2, sq);
        oidx[j] = (unsigned short)oi;
        inv[oi] = (unsigned short)j;
    }
    __syncthreads();

    const int s = blockIdx.x * 128 + qt;   // query's sorted slot
    const float4 me = pts[s];
    const int orig_q = oidx[s];
    const float n2x = -2.0f * me.x, n2y = -2.0f * me.y, n2z = -2.0f * me.z;

    unsigned long long arr[KNN];
    #pragma unroll
    for (int k = 0; k < KNN; ++k) arr[k] = SENTINEL;
    float thrF   = __int_as_float(0x7f800000);  // exact-domain 16th best
    float thrRHS = __int_as_float(0x7f800000);  // filter rhs

    const unsigned sp0 = stkBase + 2u * (unsigned)tid;
    unsigned sp = sp0;

    auto flush = [&]() {
        unsigned end = sp;
        for (unsigned j = sp0; j < end; j += TPB * 2) {
            int ja = *(const unsigned short*)(smem + j);
            float4 p = pts[ja];
            float inner = fmaf(me.z, p.z, fmaf(me.y, p.y, __fmul_rn(me.x, p.x)));
            float t  = __fadd_rn(me.w, p.w);
            float d2 = fmaf(-2.0f, inner, t);  // EXACT verified sequence
            unsigned long long carry =
                ((unsigned long long)fmap(d2) << 32) | (unsigned int)oidx[ja];
            #pragma unroll
            for (int i = 0; i < KNN; ++i) {
                bool c = carry < arr[i];
                unsigned long long lo = c ? carry : arr[i];
                carry                 = c ? arr[i] : carry;
                arr[i] = lo;
            }
        }
        sp = sp0;
        unsigned int hb = (unsigned int)(arr[KNN - 1] >> 32);
        unsigned int uf = (hb & 0x80000000u) ? (hb ^ 0x80000000u) : ~hb;  // unmap
        thrF = __uint_as_float(uf);
        thrRHS = (thrF - me.w) + EPS;
    };

    const unsigned spLimit = sp0 + (CAP - 8) * (TPB * 2);
    const int dir = h ? -1 : 1;
    int j = h ? (s - 1) : s;
    int remaining = h ? s : (NPTS - s);
    const float inff = __int_as_float(0x7f800000);

    while (remaining > 0) {
        float zlast = 0.0f;
        #pragma unroll
        for (int u = 0; u < 8; ++u) {
            int jj = j + dir * u;
            unsigned ja = ((unsigned)jj) & (NPTS - 1);
            float4 p = pts[ja];
            float lhs = fmaf(p.x, n2x, fmaf(p.y, n2y, fmaf(p.z, n2z, p.w)));
            bool inb = ((unsigned)jj) < (unsigned)NPTS;
            lhs = inb ? lhs : inff;                       // poison out-of-range
            *(unsigned short*)(smem + sp) = (unsigned short)ja;
            sp += (lhs < thrRHS) ? (TPB * 2) : 0;
            zlast = p.z;
        }
        j += dir * 8;
        remaining -= 8;
        float dz = zlast - me.z;
        float dz2 = dz * dz;
        if (dz2 > thrF + TMARG) {       // stale check first; confirm after flush
            flush();
            if (dz2 > thrF + TMARG) break;
        }
        if (sp >= spLimit) flush();
    }
    flush();

    // merge: h=1 publishes its 16 keys, h=0 inserts them (exact union)
    unsigned long long* mrg = (unsigned long long*)(smem + stkBase);
    __syncthreads();
    if (h == 1) {
        #pragma unroll
        for (int k = 0; k < KNN; ++k) mrg[k * 128 + qt] = arr[k];
    }
    __syncthreads();
    if (h == 0) {
        #pragma unroll
        for (int k = 0; k < KNN; ++k) {
            unsigned long long carry = mrg[k * 128 + qt];
            #pragma unroll
            for (int i = 0; i < KNN; ++i) {
                bool c = carry < arr[i];
                unsigned long long lo = c ? carry : arr[i];
                carry                 = c ? arr[i] : carry;
                arr[i] = lo;
            }
        }

        // arr sorted ascending by (d2, orig idx) == lax.top_k(-d2) order
        float4 nb[KNN];
        #pragma unroll
        for (int k = 0; k < KNN; ++k) nb[k] = pts[inv[(unsigned int)arr[k] & 0xFFFFu]];

        // score: reduce k first (tree16 per coordinate), then sequentially over d
        float vx[KNN], vy[KNN], vz[KNN];
        #pragma unroll
        for (int k = 0; k < KNN; ++k) {
            float tx = __fsub_rn(nb[k].x, me.x);
            float ty = __fsub_rn(nb[k].y, me.y);
            float tz = __fsub_rn(nb[k].z, me.z);
            vx[k] = __fmul_rn(tx, tx);
            vy[k] = __fmul_rn(ty, ty);
            vz[k] = __fmul_rn(tz, tz);
        }
        float score = __fadd_rn(__fadd_rn(tree16(vx), tree16(vy)), tree16(vz));
        g_scores[b * NPTS + orig_q] = score;
    }
}

// ---------------------------------------------------------------------------
// Kernel 2: per-batch bitonic sort of 4096 score keys (desc score, asc idx).
// ---------------------------------------------------------------------------
__global__ void __launch_bounds__(1024) sort_kernel() {
    __shared__ unsigned long long sh[NPTS];
    const int b = blockIdx.x, tid = threadIdx.x;

    for (int i = tid; i < NPTS; i += 1024) {
        unsigned int ub = fmap(g_scores[b * NPTS + i]);
        sh[i] = (((unsigned long long)(~ub)) << 32) | (unsigned int)i;
    }
    __syncthreads();

    for (int k = 2; k <= NPTS; k <<= 1) {
        for (int j = k >> 1; j > 0; j >>= 1) {
            #pragma unroll 2
            for (int p = tid; p < NPTS / 2; p += 1024) {
                int i = ((p & ~(j - 1)) << 1) | (p & (j - 1));
                int l = i | j;
                unsigned long long Av = sh[i], Bv = sh[l];
                bool up = ((i & k) == 0);
                if ((Av > Bv) == up) { sh[i] = Bv; sh[l] = Av; }
            }
            __syncthreads();
        }
    }
    for (int j = tid; j < NDS; j += 1024)
        g_idx[b * NDS + j] = (int)(unsigned int)sh[j];
}

// ---------------------------------------------------------------------------
// Kernel 3: gather. out = [xyz (8*3*2048) | points (8*128*2048)]
// ---------------------------------------------------------------------------
__global__ void gather_kernel(const float* __restrict__ x,
                              const float* __restrict__ y,
                              float* __restrict__ out) {
    int t = blockIdx.x * blockDim.x + threadIdx.x;
    const int XYZ = BATCH * 3 * NDS;
    if (t < XYZ) {
        int j = t % NDS;
        int rest = t / NDS;
        int d = rest % 3;
        int b = rest / 3;
        int src = g_idx[b * NDS + j];
        out[t] = x[(b * 3 + d) * NPTS + src];
    } else {
        int t2 = t - XYZ;
        if (t2 < BATCH * CH * NDS) {
            int j = t2 % NDS;
            int rest = t2 / NDS;
            int c = rest % CH;
            int b = rest / CH;
            int src = g_idx[b * NDS + j];
            out[XYZ + t2] = y[(b * CH + c) * NPTS + src];
        }
    }
}

extern "C" void kernel_launch(void* const* d_in, const int* in_sizes, int n_in,
                              void* d_out, int out_size) {
    const float* x = (const float*)d_in[0];
    const float* y = (const float*)d_in[1];
    float* out = (float*)d_out;

    static const size_t kSmem = 81920 + CAP * TPB * 2;  // 112KB
    cudaFuncSetAttribute(knn_score_kernel,
                         cudaFuncAttributeMaxDynamicSharedMemorySize, (int)kSmem);

    zsort_kernel<<<BATCH, 1024>>>(x);
    dim3 gridA(NPTS / 128, BATCH);
    knn_score_kernel<<<gridA, TPB, kSmem>>>(x);
    sort_kernel<<<BATCH, 1024>>>();

    const int total = BATCH * 3 * NDS + BATCH * CH * NDS;
    gather_kernel<<<(total + 255) / 256, 256>>>(x, y, out);
}

// round 14
// speedup vs baseline: 4.0825x; 4.0825x over previous
#include <cuda_runtime.h>
#include <cstdint>

#define BATCH 8
#define NPTS  4096
#define CH    128
#define KNN   16
#define NDS   2048
#define CAP   64     // per-thread u16 stack capacity
#define TPB   256
#define WIN0  512    // initial one-sided window (ranks)
#define WEXT  256    // extension chunk (ranks)
#define EPS   1e-3f  // conservative filter margin (approx filter domain)
#define TMARG 1e-4f  // termination margin (exact d2 domain, >> fp rounding)

// scratch (allocation-free rule: device globals)
__device__ float g_scores[BATCH * NPTS];
__device__ int   g_idx[BATCH * NDS];
__device__ int   g_zperm[BATCH * NPTS];

// XLA:GPU small-row reduction order for a 16-element row (shfl_down 8,4,2,1)
__device__ __forceinline__ float tree16(const float* v) {
    float s8[8], s4[4], s2[2];
    #pragma unroll
    for (int l = 0; l < 8; ++l) s8[l] = __fadd_rn(v[l], v[l + 8]);
    #pragma unroll
    for (int l = 0; l < 4; ++l) s4[l] = __fadd_rn(s8[l], s8[l + 4]);
    #pragma unroll
    for (int l = 0; l < 2; ++l) s2[l] = __fadd_rn(s4[l], s4[l + 2]);
    return __fadd_rn(s2[0], s2[1]);
}

__device__ __forceinline__ unsigned int fmap(float f) {
    unsigned int u = __float_as_uint(f);
    return u ^ (((unsigned int)(((int)u) >> 31)) | 0x80000000u);
}

// Sentinel = mapped(+inf) in high word: unmaps back to +inf.
#define SENTINEL 0xFF800000FFFFFFFFull

// ---------------------------------------------------------------------------
// Kernel 0: per-batch bitonic sort by z -> permutation (ascending z, idx ties)
// ---------------------------------------------------------------------------
__global__ void __launch_bounds__(1024) zsort_kernel(const float* __restrict__ x) {
    __shared__ unsigned long long sh[NPTS];
    const int b = blockIdx.x, tid = threadIdx.x;
    const float* zb = x + b * 3 * NPTS + 2 * NPTS;

    for (int i = tid; i < NPTS; i += 1024)
        sh[i] = (((unsigned long long)fmap(zb[i])) << 32) | (unsigned int)i;
    __syncthreads();

    for (int k = 2; k <= NPTS; k <<= 1) {
        for (int j = k >> 1; j > 0; j >>= 1) {
            #pragma unroll 2
            for (int p = tid; p < NPTS / 2; p += 1024) {
                int i = ((p & ~(j - 1)) << 1) | (p & (j - 1));
                int l = i | j;
                unsigned long long Av = sh[i], Bv = sh[l];
                bool up = ((i & k) == 0);
                if ((Av > Bv) == up) { sh[i] = Bv; sh[l] = Av; }
            }
            __syncthreads();
        }
    }
    for (int j = tid; j < NPTS; j += 1024)
        g_zperm[b * NPTS + j] = (int)(unsigned int)sh[j];
}

// ---------------------------------------------------------------------------
// Kernel 1: KNN score over z-SORTED candidates, fixed window + warp-uniform
// extension. 2 threads/query: h=0 scans rightward, h=1 leftward. Scan body
// = verified R12 structure (3-FFMA conservative filter, unconditional STS,
// predicated byte-cursor advance, ballot-gated flush). Exact flush recomputes
// d2 (verified sequence) into sorted u64 (mapped_d2, ORIG idx) keys.
// Termination per side: exhausted, or first-unscanned dz^2 > thrF + TMARG
// (z-monotone lower bound, strict) -- checked at warp-uniform points; warp
// ballot drives uniform 256-rank extensions (non-needing lanes push nothing).
// ---------------------------------------------------------------------------
__global__ void __launch_bounds__(TPB) knn_score_kernel(const float* __restrict__ x) {
    extern __shared__ unsigned char smem[];
    float4*         pts  = (float4*)smem;                         // 64KB sorted pts
    unsigned short* oidx = (unsigned short*)(smem + 65536);       // 8KB orig idx
    unsigned short* inv  = (unsigned short*)(smem + 73728);       // 8KB orig->sorted
    const unsigned  stkBase = 81920u;                             // 32KB stacks

    const int b   = blockIdx.y;
    const int tid = threadIdx.x;
    const int qt  = tid & 127;
    const int h   = tid >> 7;
    const float* xb = x + b * 3 * NPTS;
    const int* zp = g_zperm + b * NPTS;

    for (int j = tid; j < NPTS; j += TPB) {
        int oi = zp[j];
        float v0 = xb[oi], v1 = xb[NPTS + oi], v2 = xb[2 * NPTS + oi];
        float sq = __fadd_rn(__fadd_rn(__fmul_rn(v0, v0), __fmul_rn(v1, v1)),
                             __fmul_rn(v2, v2));
        pts[j] = make_float4(v0, v1, v2, sq);
        oidx[j] = (unsigned short)oi;
        inv[oi] = (unsigned short)j;
    }
    __syncthreads();

    const int s = blockIdx.x * 128 + qt;   // query's sorted slot
    const float4 me = pts[s];
    const int orig_q = oidx[s];
    const float n2x = -2.0f * me.x, n2y = -2.0f * me.y, n2z = -2.0f * me.z;
    const float inff  = __int_as_float(0x7f800000);
    const float ninff = __int_as_float(0xff800000);

    unsigned long long arr[KNN];
    #pragma unroll
    for (int k = 0; k < KNN; ++k) arr[k] = SENTINEL;
    float thrF   = inff;   // exact-domain 16th best
    float thrRHS = inff;   // filter rhs

    const unsigned sp0 = stkBase + 2u * (unsigned)tid;
    unsigned sp = sp0;

    auto flush = [&]() {
        unsigned end = sp;
        for (unsigned j = sp0; j < end; j += TPB * 2) {
            int ja = *(const unsigned short*)(smem + j);
            float4 p = pts[ja];
            float inner = fmaf(me.z, p.z, fmaf(me.y, p.y, __fmul_rn(me.x, p.x)));
            float t  = __fadd_rn(me.w, p.w);
            float d2 = fmaf(-2.0f, inner, t);  // EXACT verified sequence
            unsigned long long carry =
                ((unsigned long long)fmap(d2) << 32) | (unsigned int)oidx[ja];
            #pragma unroll
            for (int i = 0; i < KNN; ++i) {
                bool c = carry < arr[i];
                unsigned long long lo = c ? carry : arr[i];
                carry                 = c ? arr[i] : carry;
                arr[i] = lo;
            }
        }
        sp = sp0;
        unsigned int hb = (unsigned int)(arr[KNN - 1] >> 32);
        unsigned int uf = (hb & 0x80000000u) ? (hb ^ 0x80000000u) : ~hb;  // unmap
        thrF = __uint_as_float(uf);
        thrRHS = (thrF - me.w) + EPS;
    };

    const unsigned spLimit = sp0 + (CAP - 32) * (TPB * 2);

    // scan 'count' ranks outward starting at offset 'offBase' (warp-uniform)
    auto scanChunk = [&](int offBase, int count) {
        for (int c0 = 0; c0 < count; c0 += 32) {
            if (__ballot_sync(0xffffffffu, sp >= spLimit)) flush();
            #pragma unroll 32
            for (int u = 0; u < 32; ++u) {
                int off = offBase + c0 + u;
                int jj = h ? (s - 1 - off) : (s + off);
                unsigned ja = ((unsigned)jj) & (NPTS - 1);
                float4 p = pts[ja];
                float lhs = fmaf(p.x, n2x, fmaf(p.y, n2y, fmaf(p.z, n2z, p.w)));
                lhs = (((unsigned)jj) < (unsigned)NPTS) ? lhs : inff;  // poison OOB
                *(unsigned short*)(smem + sp) = (unsigned short)ja;
                sp += (lhs < thrRHS) ? (TPB * 2) : 0;
            }
        }
    };

    scanChunk(0, WIN0);
    flush();
    int scanned = WIN0;

    while (scanned < NPTS) {
        int nextJ = h ? (s - 1 - scanned) : (s + scanned);   // first unscanned
        bool exhausted = ((unsigned)nextJ) >= (unsigned)NPTS;
        bool need = !exhausted;
        if (need) {
            float dz = pts[(unsigned)nextJ & (NPTS - 1)].z - me.z;
            need = !(dz * dz > thrF + TMARG);
        }
        if (!__ballot_sync(0xffffffffu, need)) break;
        if (!need) thrRHS = ninff;       // no pushes for satisfied lanes
        scanChunk(scanned, WEXT);
        flush();                          // uniform; also restores thrRHS
        scanned += WEXT;
    }

    // merge: h=1 publishes its 16 keys, h=0 inserts them (exact union)
    unsigned long long* mrg = (unsigned long long*)(smem + stkBase);
    __syncthreads();
    if (h == 1) {
        #pragma unroll
        for (int k = 0; k < KNN; ++k) mrg[k * 128 + qt] = arr[k];
    }
    __syncthreads();
    if (h == 0) {
        #pragma unroll
        for (int k = 0; k < KNN; ++k) {
            unsigned long long carry = mrg[k * 128 + qt];
            #pragma unroll
            for (int i = 0; i < KNN; ++i) {
                bool c = carry < arr[i];
                unsigned long long lo = c ? carry : arr[i];
                carry                 = c ? arr[i] : carry;
                arr[i] = lo;
            }
        }

        // arr sorted ascending by (d2, orig idx) == lax.top_k(-d2) order
        float4 nb[KNN];
        #pragma unroll
        for (int k = 0; k < KNN; ++k) nb[k] = pts[inv[(unsigned int)arr[k] & 0xFFFFu]];

        // score: reduce k first (tree16 per coordinate), then sequentially over d
        float vx[KNN], vy[KNN], vz[KNN];
        #pragma unroll
        for (int k = 0; k < KNN; ++k) {
            float tx = __fsub_rn(nb[k].x, me.x);
            float ty = __fsub_rn(nb[k].y, me.y);
            float tz = __fsub_rn(nb[k].z, me.z);
            vx[k] = __fmul_rn(tx, tx);
            vy[k] = __fmul_rn(ty, ty);
            vz[k] = __fmul_rn(tz, tz);
        }
        float score = __fadd_rn(__fadd_rn(tree16(vx), tree16(vy)), tree16(vz));
        g_scores[b * NPTS + orig_q] = score;
    }
}

// ---------------------------------------------------------------------------
// Kernel 2: per-batch bitonic sort of 4096 score keys (desc score, asc idx).
// ---------------------------------------------------------------------------
__global__ void __launch_bounds__(1024) sort_kernel() {
    __shared__ unsigned long long sh[NPTS];
    const int b = blockIdx.x, tid = threadIdx.x;

    for (int i = tid; i < NPTS; i += 1024) {
        unsigned int ub = fmap(g_scores[b * NPTS + i]);
        sh[i] = (((unsigned long long)(~ub)) << 32) | (unsigned int)i;
    }
    __syncthreads();

    for (int k = 2; k <= NPTS; k <<= 1) {
        for (int j = k >> 1; j > 0; j >>= 1) {
            #pragma unroll 2
            for (int p = tid; p < NPTS / 2; p += 1024) {
                int i = ((p & ~(j - 1)) << 1) | (p & (j - 1));
                int l = i | j;
                unsigned long long Av = sh[i], Bv = sh[l];
                bool up = ((i & k) == 0);
                if ((Av > Bv) == up) { sh[i] = Bv; sh[l] = Av; }
            }
            __syncthreads();
        }
    }
    for (int j = tid; j < NDS; j += 1024)
        g_idx[b * NDS + j] = (int)(unsigned int)sh[j];
}

// ---------------------------------------------------------------------------
// Kernel 3: gather. out = [xyz (8*3*2048) | points (8*128*2048)]
// ---------------------------------------------------------------------------
__global__ void gather_kernel(const float* __restrict__ x,
                              const float* __restrict__ y,
                              float* __restrict__ out) {
    int t = blockIdx.x * blockDim.x + threadIdx.x;
    const int XYZ = BATCH * 3 * NDS;
    if (t < XYZ) {
        int j = t % NDS;
        int rest = t / NDS;
        int d = rest % 3;
        int b = rest / 3;
        int src = g_idx[b * NDS + j];
        out[t] = x[(b * 3 + d) * NPTS + src];
    } else {
        int t2 = t - XYZ;
        if (t2 < BATCH * CH * NDS) {
            int j = t2 % NDS;
            int rest = t2 / NDS;
            int c = rest % CH;
            int b = rest / CH;
            int src = g_idx[b * NDS + j];
            out[XYZ + t2] = y[(b * CH + c) * NPTS + src];
        }
    }
}

extern "C" void kernel_launch(void* const* d_in, const int* in_sizes, int n_in,
                              void* d_out, int out_size) {
    const float* x = (const float*)d_in[0];
    const float* y = (const float*)d_in[1];
    float* out = (float*)d_out;

    static const size_t kSmem = 81920 + CAP * TPB * 2;  // 112KB
    cudaFuncSetAttribute(knn_score_kernel,
                         cudaFuncAttributeMaxDynamicSharedMemorySize, (int)kSmem);

    zsort_kernel<<<BATCH, 1024>>>(x);
    dim3 gridA(NPTS / 128, BATCH);
    knn_score_kernel<<<gridA, TPB, kSmem>>>(x);
    sort_kernel<<<BATCH, 1024>>>();

    const int total = BATCH * 3 * NDS + BATCH * CH * NDS;
    gather_kernel<<<(total + 255) / 256, 256>>>(x, y, out);
}

// round 15
// speedup vs baseline: 4.6213x; 1.1320x over previous
#include <cuda_runtime.h>
#include <cstdint>

#define BATCH 8
#define NPTS  4096
#define CH    128
#define KNN   16
#define NDS   2048
#define HALF  (NPTS / 2)
#define TPB   256
#define EPS   1e-3f // conservative filter margin (>= 20x worst-case rounding slack)
#define NCUR  4     // interleaved stack cursors (break FSETP->IADD serial chain)
#define SLOTB (TPB * 2)          // bytes per slot row
#define CSTRD (NCUR * SLOTB)     // per-cursor advance stride

// scratch (allocation-free rule: device globals)
__device__ float g_scores[BATCH * NPTS];
__device__ int   g_idx[BATCH * NDS];

// XLA:GPU small-row reduction order for a 16-element row (shfl_down 8,4,2,1)
__device__ __forceinline__ float tree16(const float* v) {
    float s8[8], s4[4], s2[2];
    #pragma unroll
    for (int l = 0; l < 8; ++l) s8[l] = __fadd_rn(v[l], v[l + 8]);
    #pragma unroll
    for (int l = 0; l < 4; ++l) s4[l] = __fadd_rn(s8[l], s8[l + 4]);
    #pragma unroll
    for (int l = 0; l < 2; ++l) s2[l] = __fadd_rn(s4[l], s4[l + 2]);
    return __fadd_rn(s2[0], s2[1]);
}

// Sentinel = mapped(+inf) in high word: unmaps back to +inf.
#define SENTINEL 0xFF800000FFFFFFFFull

// ---------------------------------------------------------------------------
// Kernel 1: per-point KNN score. TWO threads per query (candidate halves).
// Hot loop (unroll 32): approximate conservative filter (3 FFMA + FSETP):
//   lhs = sq_m - 2<p,q>  vs  rhs = (thr16 - sq_q) + EPS.
// Push = unconditional STS + predicated cursor advance, spread across FOUR
// interleaved per-thread stacks (cursor mm&3) so the FSETP->IADD dependency
// no longer serializes consecutive candidates. Rare flushes drain all 4
// sub-stacks, recomputing EXACT d2 (verified sequence) into the exact sorted
// top-16 (u64 (mapped_d2,idx) carry chain in registers; insertion order
// irrelevant). Halves merged exactly at the end.
// ---------------------------------------------------------------------------
__global__ void __launch_bounds__(TPB) knn_score_kernel(const float* __restrict__ x) {
    extern __shared__ unsigned char smem[];
    float4* pts = (float4*)smem;                                   // 64KB
    const unsigned stkBase = (unsigned)(NPTS * 16);                // stacks: 48KB

    const int b   = blockIdx.y;
    const int tid = threadIdx.x;
    const int qt  = tid & 127;     // query slot within block
    const int h   = tid >> 7;      // candidate half
    const float* xb = x + b * 3 * NPTS;

    for (int m = tid; m < NPTS; m += TPB) {
        float v0 = xb[m], v1 = xb[NPTS + m], v2 = xb[2 * NPTS + m];
        float sq = __fadd_rn(__fadd_rn(__fmul_rn(v0, v0), __fmul_rn(v1, v1)),
                             __fmul_rn(v2, v2));
        pts[m] = make_float4(v0, v1, v2, sq);
    }
    __syncthreads();

    const int q = blockIdx.x * 128 + qt;
    const float4 me = pts[q];
    const float n2x = -2.0f * me.x, n2y = -2.0f * me.y, n2z = -2.0f * me.z;

    unsigned long long arr[KNN];
    #pragma unroll
    for (int k = 0; k < KNN; ++k) arr[k] = SENTINEL;
    float thrRHS = __int_as_float(0x7f800000);  // filter rhs = thr - sq_q + EPS

    // 4 interleaved byte cursors; cursor c base = stkBase + 2*tid + c*SLOTB
    const unsigned spb = stkBase + 2u * (unsigned)tid;
    unsigned sp[NCUR];
    #pragma unroll
    for (int c = 0; c < NCUR; ++c) sp[c] = spb + c * SLOTB;

    auto flush = [&]() {
        #pragma unroll
        for (int c = 0; c < NCUR; ++c) {
            unsigned beg = spb + c * SLOTB;
            unsigned end = sp[c];
            for (unsigned j = beg; j < end; j += CSTRD) {
                int m = *(const unsigned short*)(smem + j);
                float4 p = pts[m];
                float inner = fmaf(me.z, p.z, fmaf(me.y, p.y, __fmul_rn(me.x, p.x)));
                float t  = __fadd_rn(me.w, p.w);
                float d2 = fmaf(-2.0f, inner, t);  // EXACT verified sequence
                unsigned int ub = __float_as_uint(d2);
                ub ^= ((unsigned int)(((int)ub) >> 31)) | 0x80000000u;
                unsigned long long carry = ((unsigned long long)ub << 32) | (unsigned int)m;
                #pragma unroll
                for (int i = 0; i < KNN; ++i) {
                    bool cc = carry < arr[i];
                    unsigned long long lo = cc ? carry : arr[i];
                    carry                 = cc ? arr[i] : carry;
                    arr[i] = lo;
                }
            }
            sp[c] = beg;
        }
        unsigned int hb = (unsigned int)(arr[KNN - 1] >> 32);
        unsigned int uf = (hb & 0x80000000u) ? (hb ^ 0x80000000u) : ~hb;  // unmap
        float thrF = __uint_as_float(uf);
        thrRHS = (thrF - me.w) + EPS;
    };

    // flush when any cursor has used > 8 slots (next 64-chunk adds <= 16/cursor;
    // per-cursor capacity is 24 slots -> never overflows the 48KB region)
    const unsigned guard = 8u * CSTRD;
    const int mbeg = h * HALF;
    for (int base = 0; base < HALF; base += 64) {
        bool full = false;
        #pragma unroll
        for (int c = 0; c < NCUR; ++c)
            full |= (sp[c] - (spb + c * SLOTB)) > guard;
        if (__any_sync(0xffffffffu, full)) flush();
        #pragma unroll 32
        for (int mm = 0; mm < 64; ++mm) {
            int m = mbeg + base + mm;
            float4 p = pts[m];  // broadcast LDS.128
            // approximate conservative filter: 3 FFMA + FSETP
            float lhs = fmaf(p.x, n2x, fmaf(p.y, n2y, fmaf(p.z, n2z, p.w)));
            *(unsigned short*)(smem + sp[mm & 3]) = (unsigned short)m;  // uncond STS
            sp[mm & 3] += (lhs < thrRHS) ? CSTRD : 0;                   // pred advance
        }
    }
    flush();

    // merge: half-1 publishes its 16 keys, half-0 inserts them (exact union)
    unsigned long long* mrg = (unsigned long long*)(smem + stkBase);
    __syncthreads();
    if (h == 1) {
        #pragma unroll
        for (int k = 0; k < KNN; ++k) mrg[k * 128 + qt] = arr[k];
    }
    __syncthreads();
    if (h == 0) {
        #pragma unroll
        for (int k = 0; k < KNN; ++k) {
            unsigned long long carry = mrg[k * 128 + qt];
            #pragma unroll
            for (int i = 0; i < KNN; ++i) {
                bool c = carry < arr[i];
                unsigned long long lo = c ? carry : arr[i];
                carry                 = c ? arr[i] : carry;
                arr[i] = lo;
            }
        }

        // arr is sorted ascending by (d2, idx) == lax.top_k(-d2) order
        float4 nb[KNN];
        #pragma unroll
        for (int k = 0; k < KNN; ++k) nb[k] = pts[(unsigned int)arr[k]];

        // score: reduce k first (tree16 per coordinate), then sequentially over d
        float vx[KNN], vy[KNN], vz[KNN];
        #pragma unroll
        for (int k = 0; k < KNN; ++k) {
            float tx = __fsub_rn(nb[k].x, me.x);
            float ty = __fsub_rn(nb[k].y, me.y);
            float tz = __fsub_rn(nb[k].z, me.z);
            vx[k] = __fmul_rn(tx, tx);
            vy[k] = __fmul_rn(ty, ty);
            vz[k] = __fmul_rn(tz, tz);
        }
        float score = __fadd_rn(__fadd_rn(tree16(vx), tree16(vy)), tree16(vz));
        g_scores[b * NPTS + q] = score;
    }
}

// ---------------------------------------------------------------------------
// Kernel 2: per-batch bitonic sort of 4096 keys, compact pair indexing.
// key = (~mapped(score) << 32) | idx -> ascending u64 = desired rank order.
// ---------------------------------------------------------------------------
__global__ void __launch_bounds__(1024) sort_kernel() {
    __shared__ unsigned long long sh[NPTS];
    const int b = blockIdx.x, tid = threadIdx.x;

    for (int i = tid; i < NPTS; i += 1024) {
        unsigned int ub = __float_as_uint(g_scores[b * NPTS + i]);
        ub ^= ((unsigned int)(((int)ub) >> 31)) | 0x80000000u;
        sh[i] = (((unsigned long long)(~ub)) << 32) | (unsigned int)i;
    }
    __syncthreads();

    for (int k = 2; k <= NPTS; k <<= 1) {
        for (int j = k >> 1; j > 0; j >>= 1) {
            #pragma unroll 2
            for (int p = tid; p < NPTS / 2; p += 1024) {
                int i = ((p & ~(j - 1)) << 1) | (p & (j - 1));
                int l = i | j;
                unsigned long long Av = sh[i], Bv = sh[l];
                bool up = ((i & k) == 0);
                if ((Av > Bv) == up) { sh[i] = Bv; sh[l] = Av; }
            }
            __syncthreads();
        }
    }
    for (int j = tid; j < NDS; j += 1024)
        g_idx[b * NDS + j] = (int)(unsigned int)sh[j];
}

// ---------------------------------------------------------------------------
// Kernel 3: gather. out = [xyz (8*3*2048) | points (8*128*2048)]
// ---------------------------------------------------------------------------
__global__ void gather_kernel(const float* __restrict__ x,
                              const float* __restrict__ y,
                              float* __restrict__ out) {
    int t = blockIdx.x * blockDim.x + threadIdx.x;
    const int XYZ = BATCH * 3 * NDS;
    if (t < XYZ) {
        int j = t % NDS;
        int rest = t / NDS;
        int d = rest % 3;
        int b = rest / 3;
        int src = g_idx[b * NDS + j];
        out[t] = x[(b * 3 + d) * NPTS + src];
    } else {
        int t2 = t - XYZ;
        if (t2 < BATCH * CH * NDS) {
            int j = t2 % NDS;
            int rest = t2 / NDS;
            int c = rest % CH;
            int b = rest / CH;
            int src = g_idx[b * NDS + j];
            out[XYZ + t2] = y[(b * CH + c) * NPTS + src];
        }
    }
}

extern "C" void kernel_launch(void* const* d_in, const int* in_sizes, int n_in,
                              void* d_out, int out_size) {
    const float* x = (const float*)d_in[0];
    const float* y = (const float*)d_in[1];
    float* out = (float*)d_out;

    static const size_t kSmem = NPTS * 16 + 96 * TPB * 2;  // 112KB (24 slots x 4 cursors)
    cudaFuncSetAttribute(knn_score_kernel,
                         cudaFuncAttributeMaxDynamicSharedMemorySize, (int)kSmem);

    dim3 gridA(NPTS / 128, BATCH);
    knn_score_kernel<<<gridA, TPB, kSmem>>>(x);
    sort_kernel<<<BATCH, 1024>>>();

    const int total = BATCH * 3 * NDS + BATCH * CH * NDS;
    gather_kernel<<<(total + 255) / 256, 256>>>(x, y, out);
}